// round 1
// baseline (speedup 1.0000x reference)
#include <cuda_runtime.h>

// Problem shape (fixed for this benchmark)
//   x:     [8, 256, 256, 64]  fp32
//   Wqkv:  [64, 192]          fp32  (cols 0:64 = Wq, 64:128 = Wk, 128:192 = Wv)
//   Wproj: [64, 64]           fp32
//   out:   [8, 256, 256, 64]  fp32
//
// Algebra: per block n (n = bi*4 + m1*2 + m2, 32 blocks):
//   G_n[e][f]   = sum_{l in block} x[l][e] * x[l][f]
//   score       = temp * Wq^T G_n Wk            (temp = 1/8)
//   W           = softmax_rows(score)
//   B_n         = Wv W^T Wproj                  (64x64)
//   y[l][:]     = x[l][:] @ B_n

#define CHUNKS 32   // K1: pixel chunks per block   -> grid 32*32 CTAs
#define CH3    64   // K3: pixel chunks per block   -> grid 32*64 CTAs

__device__ __align__(16) float g_part[32 * CHUNKS * 4096]; // per-chunk Gram partials
__device__ __align__(16) float g_B[32 * 4096];             // per-block 64x64 B matrices

// ---------- packed f32x2 helpers (Blackwell FFMA2 path) ----------
__device__ __forceinline__ unsigned long long fma2(unsigned long long a,
                                                   unsigned long long b,
                                                   unsigned long long c) {
    unsigned long long d;
    asm("fma.rn.f32x2 %0, %1, %2, %3;" : "=l"(d) : "l"(a), "l"(b), "l"(c));
    return d;
}
__device__ __forceinline__ unsigned long long add2(unsigned long long a,
                                                   unsigned long long b) {
    unsigned long long d;
    asm("add.rn.f32x2 %0, %1, %2;" : "=l"(d) : "l"(a), "l"(b));
    return d;
}
__device__ __forceinline__ unsigned long long pack2(float lo, float hi) {
    unsigned long long d;
    asm("mov.b64 %0, {%1, %2};" : "=l"(d) : "f"(lo), "f"(hi));
    return d;
}
__device__ __forceinline__ void unpack2(unsigned long long v, float& lo, float& hi) {
    asm("mov.b64 {%0, %1}, %2;" : "=f"(lo), "=f"(hi) : "l"(v));
}

// =====================================================================
// K1: per-block Gram partials.  CTA = (chunk, block), 256 threads.
// Each thread owns a 4x4 tile of the 64x64 Gram, accumulated in f32x2 pairs.
// =====================================================================
__global__ __launch_bounds__(256) void gram_kernel(const float* __restrict__ x) {
    const int n  = blockIdx.y;           // block 0..31
    const int ch = blockIdx.x;           // chunk 0..CHUNKS-1
    const int bi = n >> 2, m1 = (n >> 1) & 1, m2 = n & 1;
    const int t  = threadIdx.x;
    const int ty = t >> 4, tx = t & 15;

    __shared__ __align__(16) float sx[8][64];

    unsigned long long acc[2][4];
#pragma unroll
    for (int i = 0; i < 2; i++)
#pragma unroll
        for (int j = 0; j < 4; j++) acc[i][j] = 0ull;  // (0.f,0.f)

    const int PPC = 16384 / CHUNKS;      // 512 pixels per CTA
    const int p0  = ch * PPC;

    for (int rr = 0; rr < PPC / 8; rr++) {
        // stage 8 pixel rows (8 x 64 floats)
        if (t < 128) {
            int pp = t >> 4, q = t & 15;
            int p  = p0 + rr * 8 + pp;
            int hi = p >> 7, wi = p & 127;
            int yy = 2 * hi + m1, xx = 2 * wi + m2;
            const float4* src =
                (const float4*)(x + ((((bi << 8) | yy) << 8 | xx) << 6));
            *(float4*)&sx[pp][q * 4] = src[q];
        }
        __syncthreads();
#pragma unroll
        for (int pp = 0; pp < 8; pp++) {
            ulonglong2 av = *(const ulonglong2*)&sx[pp][ty * 4]; // rows 4ty..4ty+3 (2 pairs)
            float4 bv = *(const float4*)&sx[pp][tx * 4];         // cols 4tx..4tx+3
            unsigned long long bd0 = pack2(bv.x, bv.x);
            unsigned long long bd1 = pack2(bv.y, bv.y);
            unsigned long long bd2 = pack2(bv.z, bv.z);
            unsigned long long bd3 = pack2(bv.w, bv.w);
            acc[0][0] = fma2(av.x, bd0, acc[0][0]);
            acc[0][1] = fma2(av.x, bd1, acc[0][1]);
            acc[0][2] = fma2(av.x, bd2, acc[0][2]);
            acc[0][3] = fma2(av.x, bd3, acc[0][3]);
            acc[1][0] = fma2(av.y, bd0, acc[1][0]);
            acc[1][1] = fma2(av.y, bd1, acc[1][1]);
            acc[1][2] = fma2(av.y, bd2, acc[1][2]);
            acc[1][3] = fma2(av.y, bd3, acc[1][3]);
        }
        __syncthreads();
    }

    float* dst = g_part + (n * CHUNKS + ch) * 4096;
#pragma unroll
    for (int ip = 0; ip < 2; ip++)
#pragma unroll
        for (int j = 0; j < 4; j++) {
            float lo, hi;
            unpack2(acc[ip][j], lo, hi);
            int r  = ty * 4 + ip * 2;
            int cc = tx * 4 + j;
            dst[r * 64 + cc]       = lo;
            dst[(r + 1) * 64 + cc] = hi;
        }
}

// =====================================================================
// K2: per-block math.  32 CTAs, 256 threads.  Everything 64x64 in smem.
// =====================================================================
__device__ __forceinline__ void mm64(float* __restrict__ C,
                                     const float* __restrict__ A,
                                     const float* __restrict__ B,
                                     int r, int c0, float scale) {
    float acc[16];
#pragma unroll
    for (int j = 0; j < 16; j++) acc[j] = 0.f;
#pragma unroll 4
    for (int k = 0; k < 64; k++) {
        float a = A[r * 64 + k];
        const float4* bp = (const float4*)(B + k * 64 + c0);
        float4 b0 = bp[0], b1 = bp[1], b2 = bp[2], b3 = bp[3];
        acc[0]  += a * b0.x; acc[1]  += a * b0.y; acc[2]  += a * b0.z; acc[3]  += a * b0.w;
        acc[4]  += a * b1.x; acc[5]  += a * b1.y; acc[6]  += a * b1.z; acc[7]  += a * b1.w;
        acc[8]  += a * b2.x; acc[9]  += a * b2.y; acc[10] += a * b2.z; acc[11] += a * b2.w;
        acc[12] += a * b3.x; acc[13] += a * b3.y; acc[14] += a * b3.z; acc[15] += a * b3.w;
    }
#pragma unroll
    for (int j = 0; j < 16; j++) C[r * 64 + c0 + j] = acc[j] * scale;
}

__global__ __launch_bounds__(256) void block_math_kernel(const float* __restrict__ Wqkv,
                                                         const float* __restrict__ Wproj) {
    const int n  = blockIdx.x;
    const int t  = threadIdx.x;
    const int r  = t >> 2;
    const int c0 = (t & 3) << 4;

    __shared__ float s0[64 * 64];
    __shared__ float s1[64 * 64];
    __shared__ float s2[64 * 64];

    // 1) reduce Gram partials into s0 (fixed order -> deterministic)
    {
        float racc[16];
#pragma unroll
        for (int j = 0; j < 16; j++) racc[j] = 0.f;
        const float* gp = g_part + n * CHUNKS * 4096 + r * 64 + c0;
        for (int chn = 0; chn < CHUNKS; chn++) {
            const float4* p4 = (const float4*)(gp + chn * 4096);
#pragma unroll
            for (int jj = 0; jj < 4; jj++) {
                float4 v = p4[jj];
                racc[jj * 4 + 0] += v.x; racc[jj * 4 + 1] += v.y;
                racc[jj * 4 + 2] += v.z; racc[jj * 4 + 3] += v.w;
            }
        }
#pragma unroll
        for (int j = 0; j < 16; j++) s0[r * 64 + c0 + j] = racc[j];
    }
    // 2) s1 = Wk  (Wqkv cols 64..127)
#pragma unroll
    for (int j = 0; j < 16; j++) s1[r * 64 + c0 + j] = Wqkv[r * 192 + 64 + c0 + j];
    __syncthreads();

    // 3) s2 = G @ Wk
    mm64(s2, s0, s1, r, c0, 1.f);
    __syncthreads();

    // 4) s1 = Wq^T  (s1[c][e] = Wqkv[e*192 + c])
#pragma unroll
    for (int j = 0; j < 16; j++) s1[r * 64 + c0 + j] = Wqkv[(c0 + j) * 192 + r];
    __syncthreads();

    // 5) s0 = temp * Wq^T @ (G Wk)   (score; overwrites G)
    mm64(s0, s1, s2, r, c0, 0.125f);
    __syncthreads();

    // 6) row softmax of s0
    if (t < 64) {
        float* row = s0 + t * 64;
        float m = row[0];
#pragma unroll 8
        for (int k = 1; k < 64; k++) m = fmaxf(m, row[k]);
        float s = 0.f;
#pragma unroll 8
        for (int k = 0; k < 64; k++) { float e = expf(row[k] - m); row[k] = e; s += e; }
        float inv = 1.f / s;
#pragma unroll 8
        for (int k = 0; k < 64; k++) row[k] *= inv;
    }
    __syncthreads();

    // 7) s2 = weight^T ; s1 = Wv (Wqkv cols 128..191)
#pragma unroll
    for (int j = 0; j < 16; j++) s2[r * 64 + c0 + j] = s0[(c0 + j) * 64 + r];
#pragma unroll
    for (int j = 0; j < 16; j++) s1[r * 64 + c0 + j] = Wqkv[r * 192 + 128 + c0 + j];
    __syncthreads();

    // 8) s0 = Wv @ weight^T
    mm64(s0, s1, s2, r, c0, 1.f);
    __syncthreads();

    // 9) s1 = Wproj;  g_B[n] = (Wv W^T) @ Wproj
#pragma unroll
    for (int j = 0; j < 16; j++) s1[r * 64 + c0 + j] = Wproj[r * 64 + c0 + j];
    __syncthreads();
    {
        float acc[16];
#pragma unroll
        for (int j = 0; j < 16; j++) acc[j] = 0.f;
#pragma unroll 4
        for (int k = 0; k < 64; k++) {
            float a = s0[r * 64 + k];
            const float4* bp = (const float4*)(s1 + k * 64 + c0);
            float4 b0 = bp[0], b1 = bp[1], b2 = bp[2], b3 = bp[3];
            acc[0]  += a * b0.x; acc[1]  += a * b0.y; acc[2]  += a * b0.z; acc[3]  += a * b0.w;
            acc[4]  += a * b1.x; acc[5]  += a * b1.y; acc[6]  += a * b1.z; acc[7]  += a * b1.w;
            acc[8]  += a * b2.x; acc[9]  += a * b2.y; acc[10] += a * b2.z; acc[11] += a * b2.w;
            acc[12] += a * b3.x; acc[13] += a * b3.y; acc[14] += a * b3.z; acc[15] += a * b3.w;
        }
        float* dst = g_B + n * 4096 + r * 64 + c0;
#pragma unroll
        for (int j = 0; j < 16; j++) dst[j] = acc[j];
    }
}

// =====================================================================
// K3: y_l = x_l @ B_n.  CTA = (chunk, block), 128 threads (4 warps).
// Thread (pg = warp, j2 = lane) computes output cols {2j2, 2j2+1} for one
// pixel per pass.  B column-pair lives entirely in registers (64 x u64);
// x is staged in smem as duplicated f32x2 pairs (warp-broadcast reads).
// =====================================================================
__global__ __launch_bounds__(128, 3) void apply_kernel(const float* __restrict__ x,
                                                       float* __restrict__ out) {
    const int n  = blockIdx.y;
    const int ch = blockIdx.x;
    const int bi = n >> 2, m1 = (n >> 1) & 1, m2 = n & 1;
    const int t  = threadIdx.x;
    const int pg = t >> 5;        // warp -> pixel slot in group of 4
    const int j2 = t & 31;        // column pair

    __shared__ __align__(16) unsigned long long xd[4][64];

    // preload B column pair: breg[k] = (B[k][2j2], B[k][2j2+1])
    unsigned long long breg[64];
    const unsigned long long* Bp =
        (const unsigned long long*)(g_B) + n * 2048;
#pragma unroll
    for (int k = 0; k < 64; k++) breg[k] = Bp[k * 32 + j2];

    const int PPC = 16384 / CH3;  // 256 pixels per CTA
    const int p0  = ch * PPC;

    for (int it = 0; it < PPC / 4; it++) {
        // stage 4 pixels as duplicated pairs
        if (t < 64) {
            int pp = t >> 4, q = t & 15;
            int p  = p0 + it * 4 + pp;
            int hi = p >> 7, wi = p & 127;
            int yy = 2 * hi + m1, xx = 2 * wi + m2;
            float4 v = *(const float4*)(x + ((((bi << 8) | yy) << 8 | xx) << 6) + q * 4);
            xd[pp][q * 4 + 0] = pack2(v.x, v.x);
            xd[pp][q * 4 + 1] = pack2(v.y, v.y);
            xd[pp][q * 4 + 2] = pack2(v.z, v.z);
            xd[pp][q * 4 + 3] = pack2(v.w, v.w);
        }
        __syncthreads();

        unsigned long long acc0 = 0ull, acc1 = 0ull;
#pragma unroll
        for (int kk = 0; kk < 16; kk++) {
            ulonglong2 xv0 = *(const ulonglong2*)&xd[pg][kk * 4];
            ulonglong2 xv1 = *(const ulonglong2*)&xd[pg][kk * 4 + 2];
            acc0 = fma2(xv0.x, breg[kk * 4 + 0], acc0);
            acc1 = fma2(xv0.y, breg[kk * 4 + 1], acc1);
            acc0 = fma2(xv1.x, breg[kk * 4 + 2], acc0);
            acc1 = fma2(xv1.y, breg[kk * 4 + 3], acc1);
        }
        unsigned long long acc = add2(acc0, acc1);

        int p  = p0 + it * 4 + pg;
        int hi = p >> 7, wi = p & 127;
        int yy = 2 * hi + m1, xx = 2 * wi + m2;
        float lo, hf;
        unpack2(acc, lo, hf);
        *(float2*)(out + ((((bi << 8) | yy) << 8 | xx) << 6) + j2 * 2) =
            make_float2(lo, hf);
        __syncthreads();
    }
}

extern "C" void kernel_launch(void* const* d_in, const int* in_sizes, int n_in,
                              void* d_out, int out_size) {
    const float* x     = (const float*)d_in[0];
    const float* Wqkv  = (const float*)d_in[1];
    const float* Wproj = (const float*)d_in[2];
    float* out = (float*)d_out;

    gram_kernel<<<dim3(CHUNKS, 32), 256>>>(x);
    block_math_kernel<<<32, 256>>>(Wqkv, Wproj);
    apply_kernel<<<dim3(CH3, 32), 128>>>(x, out);
}

// round 2
// speedup vs baseline: 1.2909x; 1.2909x over previous
#include <cuda_runtime.h>

// Problem shape (fixed)
//   x:     [8, 256, 256, 64] fp32   Wqkv: [64,192]   Wproj: [64,64]
//   out:   [8, 256, 256, 64] fp32
// Per block n (bi*4+m1*2+m2):
//   G = sum_l x_l x_l^T ; score = Wq^T G Wk / 8 ; W = softmax_rows(score)
//   B = Wv W^T Wproj ; y_l = x_l B

#define GCH 32   // gram chunks per block -> grid (32,32)
#define ACH 64   // apply chunks per block -> grid (64,32)

__device__ __align__(16) float g_part[32 * GCH * 4 * 4096]; // 64MB partial Grams
__device__ __align__(16) float g_G[32 * 4096];              // reduced Grams
__device__ __align__(16) float g_B[32 * 4096];              // per-block B

typedef unsigned long long ull;

__device__ __forceinline__ ull fma2(ull a, ull b, ull c) {
    ull d; asm("fma.rn.f32x2 %0, %1, %2, %3;" : "=l"(d) : "l"(a), "l"(b), "l"(c));
    return d;
}
__device__ __forceinline__ ull pack2(float lo, float hi) {
    ull d; asm("mov.b64 %0, {%1, %2};" : "=l"(d) : "f"(lo), "f"(hi));
    return d;
}
__device__ __forceinline__ void unpack2(ull v, float& lo, float& hi) {
    asm("mov.b64 {%0, %1}, %2;" : "=f"(lo), "=f"(hi) : "l"(v));
}

// pixel p (0..16383) -> float offset of its 64-channel row in x/out
__device__ __forceinline__ int rowoff(int bi, int m1, int m2, int p) {
    int hi = p >> 7, wi = p & 127;
    int yy = 2 * hi + m1, xx = 2 * wi + m2;
    return ((((bi << 8) | yy) << 8) | xx) << 6;
}

// =====================================================================
// K1: Gram partials. grid (GCH,32), 256 thr = 4 groups x 64.
// Thread owns an 8x8 tile (as 8 rows x 4 f32x2 col-pairs).
// 2-buffer smem pipeline, LDG issued one stage ahead.
// =====================================================================
__global__ __launch_bounds__(256, 2) void gram_kernel(const float* __restrict__ x) {
    const int n = blockIdx.y, ch = blockIdx.x;
    const int bi = n >> 2, m1 = (n >> 1) & 1, m2 = n & 1;
    const int t = threadIdx.x;
    const int g = t >> 6, ts = t & 63;
    const int i = ts >> 3, j = ts & 7;

    __shared__ __align__(16) float sx[2][32][64];

    const int PPC = 16384 / GCH;   // 512
    const int NIT = PPC / 32;      // 16
    const int p0  = ch * PPC;

    // loader: thread covers (plA, q) and (plA+16, q)
    const int q = t & 15, plA = t >> 4;

    ull acc[8][4];
#pragma unroll
    for (int r = 0; r < 8; r++)
#pragma unroll
        for (int m = 0; m < 4; m++) acc[r][m] = 0ull;

    float4 rA, rB;
    // prologue: it=0 load+store, it=1 load
    {
        int p = p0 + plA;
        rA = *((const float4*)(x + rowoff(bi, m1, m2, p)) + q);
        p = p0 + plA + 16;
        rB = *((const float4*)(x + rowoff(bi, m1, m2, p)) + q);
        *(float4*)&sx[0][plA][q * 4] = rA;
        *(float4*)&sx[0][plA + 16][q * 4] = rB;
        p = p0 + 32 + plA;
        rA = *((const float4*)(x + rowoff(bi, m1, m2, p)) + q);
        p = p0 + 32 + plA + 16;
        rB = *((const float4*)(x + rowoff(bi, m1, m2, p)) + q);
    }
    __syncthreads();

    for (int it = 0; it < NIT; it++) {
        const float (*buf)[64] = sx[it & 1];
#pragma unroll
        for (int pp = 0; pp < 8; pp++) {
            const float* row = &buf[g * 8 + pp][0];
            float4 a0 = *(const float4*)&row[i * 8];
            float4 a1 = *(const float4*)&row[i * 8 + 4];
            ulonglong2 b01 = *(const ulonglong2*)&row[j * 8];
            ulonglong2 b23 = *(const ulonglong2*)&row[j * 8 + 4];
            ull ad;
            ad = pack2(a0.x, a0.x);
            acc[0][0]=fma2(ad,b01.x,acc[0][0]); acc[0][1]=fma2(ad,b01.y,acc[0][1]);
            acc[0][2]=fma2(ad,b23.x,acc[0][2]); acc[0][3]=fma2(ad,b23.y,acc[0][3]);
            ad = pack2(a0.y, a0.y);
            acc[1][0]=fma2(ad,b01.x,acc[1][0]); acc[1][1]=fma2(ad,b01.y,acc[1][1]);
            acc[1][2]=fma2(ad,b23.x,acc[1][2]); acc[1][3]=fma2(ad,b23.y,acc[1][3]);
            ad = pack2(a0.z, a0.z);
            acc[2][0]=fma2(ad,b01.x,acc[2][0]); acc[2][1]=fma2(ad,b01.y,acc[2][1]);
            acc[2][2]=fma2(ad,b23.x,acc[2][2]); acc[2][3]=fma2(ad,b23.y,acc[2][3]);
            ad = pack2(a0.w, a0.w);
            acc[3][0]=fma2(ad,b01.x,acc[3][0]); acc[3][1]=fma2(ad,b01.y,acc[3][1]);
            acc[3][2]=fma2(ad,b23.x,acc[3][2]); acc[3][3]=fma2(ad,b23.y,acc[3][3]);
            ad = pack2(a1.x, a1.x);
            acc[4][0]=fma2(ad,b01.x,acc[4][0]); acc[4][1]=fma2(ad,b01.y,acc[4][1]);
            acc[4][2]=fma2(ad,b23.x,acc[4][2]); acc[4][3]=fma2(ad,b23.y,acc[4][3]);
            ad = pack2(a1.y, a1.y);
            acc[5][0]=fma2(ad,b01.x,acc[5][0]); acc[5][1]=fma2(ad,b01.y,acc[5][1]);
            acc[5][2]=fma2(ad,b23.x,acc[5][2]); acc[5][3]=fma2(ad,b23.y,acc[5][3]);
            ad = pack2(a1.z, a1.z);
            acc[6][0]=fma2(ad,b01.x,acc[6][0]); acc[6][1]=fma2(ad,b01.y,acc[6][1]);
            acc[6][2]=fma2(ad,b23.x,acc[6][2]); acc[6][3]=fma2(ad,b23.y,acc[6][3]);
            ad = pack2(a1.w, a1.w);
            acc[7][0]=fma2(ad,b01.x,acc[7][0]); acc[7][1]=fma2(ad,b01.y,acc[7][1]);
            acc[7][2]=fma2(ad,b23.x,acc[7][2]); acc[7][3]=fma2(ad,b23.y,acc[7][3]);
        }
        if (it + 1 < NIT) {  // store data for it+1 (loaded last iteration)
            int b = (it + 1) & 1;
            *(float4*)&sx[b][plA][q * 4] = rA;
            *(float4*)&sx[b][plA + 16][q * 4] = rB;
        }
        if (it + 2 < NIT) {  // load data for it+2
            int p = p0 + (it + 2) * 32 + plA;
            rA = *((const float4*)(x + rowoff(bi, m1, m2, p)) + q);
            p += 16;
            rB = *((const float4*)(x + rowoff(bi, m1, m2, p)) + q);
        }
        __syncthreads();
    }

    float* dst = g_part + ((size_t)((n * GCH + ch) * 4 + g)) * 4096;
#pragma unroll
    for (int r = 0; r < 8; r++) {
        ulonglong2 v0; v0.x = acc[r][0]; v0.y = acc[r][1];
        ulonglong2 v1; v1.x = acc[r][2]; v1.y = acc[r][3];
        *(ulonglong2*)&dst[(i * 8 + r) * 64 + j * 8] = v0;
        *(ulonglong2*)&dst[(i * 8 + r) * 64 + j * 8 + 4] = v1;
    }
}

// =====================================================================
// K1.5: reduce 128 partials per block. grid (8,32), 128 thr.
// =====================================================================
__global__ __launch_bounds__(128) void reduce_kernel() {
    const int n = blockIdx.y, sl = blockIdx.x, t = threadIdx.x;
    const int off = sl * 512 + t * 4;
    const float* base = g_part + (size_t)n * (GCH * 4) * 4096 + off;
    float4 a = make_float4(0.f, 0.f, 0.f, 0.f);
#pragma unroll 4
    for (int c = 0; c < GCH * 4; c++) {
        float4 v = *(const float4*)(base + (size_t)c * 4096);
        a.x += v.x; a.y += v.y; a.z += v.z; a.w += v.w;
    }
    *(float4*)(g_G + n * 4096 + off) = a;
}

// =====================================================================
// K2: per-block 64x64 math chain. 32 CTAs x 256 thr.
// =====================================================================
__device__ __forceinline__ void mm64(float* __restrict__ C,
                                     const float* __restrict__ A,
                                     const float* __restrict__ B,
                                     int r, int c0, float scale) {
    float acc[16];
#pragma unroll
    for (int j = 0; j < 16; j++) acc[j] = 0.f;
#pragma unroll 4
    for (int k = 0; k < 64; k++) {
        float a = A[r * 64 + k];
        const float4* bp = (const float4*)(B + k * 64 + c0);
        float4 b0 = bp[0], b1 = bp[1], b2 = bp[2], b3 = bp[3];
        acc[0]  += a * b0.x; acc[1]  += a * b0.y; acc[2]  += a * b0.z; acc[3]  += a * b0.w;
        acc[4]  += a * b1.x; acc[5]  += a * b1.y; acc[6]  += a * b1.z; acc[7]  += a * b1.w;
        acc[8]  += a * b2.x; acc[9]  += a * b2.y; acc[10] += a * b2.z; acc[11] += a * b2.w;
        acc[12] += a * b3.x; acc[13] += a * b3.y; acc[14] += a * b3.z; acc[15] += a * b3.w;
    }
#pragma unroll
    for (int j = 0; j < 16; j++) C[r * 64 + c0 + j] = acc[j] * scale;
}

__global__ __launch_bounds__(256) void block_math_kernel(const float* __restrict__ Wqkv,
                                                         const float* __restrict__ Wproj) {
    const int n = blockIdx.x, t = threadIdx.x;
    const int r = t >> 2, c0 = (t & 3) << 4;

    __shared__ float s0[4096];
    __shared__ float s1[4096];
    __shared__ float s2[4096];

    // G into s0 ; Wk into s1
#pragma unroll
    for (int j = 0; j < 16; j++) s0[r * 64 + c0 + j] = g_G[n * 4096 + r * 64 + c0 + j];
#pragma unroll
    for (int j = 0; j < 16; j++) s1[r * 64 + c0 + j] = Wqkv[r * 192 + 64 + c0 + j];
    __syncthreads();

    mm64(s2, s0, s1, r, c0, 1.f);           // s2 = G Wk
    __syncthreads();
#pragma unroll
    for (int j = 0; j < 16; j++) s1[r * 64 + c0 + j] = Wqkv[(c0 + j) * 192 + r]; // Wq^T
    __syncthreads();
    mm64(s0, s1, s2, r, c0, 0.125f);        // score
    __syncthreads();

    if (t < 64) {                            // row softmax
        float* row = s0 + t * 64;
        float m = row[0];
#pragma unroll 8
        for (int k = 1; k < 64; k++) m = fmaxf(m, row[k]);
        float s = 0.f;
#pragma unroll 8
        for (int k = 0; k < 64; k++) { float e = expf(row[k] - m); row[k] = e; s += e; }
        float inv = 1.f / s;
#pragma unroll 8
        for (int k = 0; k < 64; k++) row[k] *= inv;
    }
    __syncthreads();

#pragma unroll
    for (int j = 0; j < 16; j++) s2[r * 64 + c0 + j] = s0[(c0 + j) * 64 + r];     // W^T
#pragma unroll
    for (int j = 0; j < 16; j++) s1[r * 64 + c0 + j] = Wqkv[r * 192 + 128 + c0 + j]; // Wv
    __syncthreads();
    mm64(s0, s1, s2, r, c0, 1.f);           // Wv W^T
    __syncthreads();
#pragma unroll
    for (int j = 0; j < 16; j++) s1[r * 64 + c0 + j] = Wproj[r * 64 + c0 + j];
    __syncthreads();
    {
        float acc[16];
#pragma unroll
        for (int j = 0; j < 16; j++) acc[j] = 0.f;
#pragma unroll 4
        for (int k = 0; k < 64; k++) {
            float a = s0[r * 64 + k];
            const float4* bp = (const float4*)(s1 + k * 64 + c0);
            float4 b0 = bp[0], b1 = bp[1], b2 = bp[2], b3 = bp[3];
            acc[0]  += a * b0.x; acc[1]  += a * b0.y; acc[2]  += a * b0.z; acc[3]  += a * b0.w;
            acc[4]  += a * b1.x; acc[5]  += a * b1.y; acc[6]  += a * b1.z; acc[7]  += a * b1.w;
            acc[8]  += a * b2.x; acc[9]  += a * b2.y; acc[10] += a * b2.z; acc[11] += a * b2.w;
            acc[12] += a * b3.x; acc[13] += a * b3.y; acc[14] += a * b3.z; acc[15] += a * b3.w;
        }
        float* dst = g_B + n * 4096 + r * 64 + c0;
#pragma unroll
        for (int j = 0; j < 16; j++) dst[j] = acc[j];
    }
}

// =====================================================================
// K3: y = x B.  grid (ACH,32), 128 thr.  B in smem, x double-buffered.
// Thread tile: 4 pixels x 8 cols (4 f32x2 col-pairs).
// =====================================================================
__global__ __launch_bounds__(128, 4) void apply_kernel(const float* __restrict__ x,
                                                       float* __restrict__ out) {
    const int n = blockIdx.y, ch = blockIdx.x;
    const int bi = n >> 2, m1 = (n >> 1) & 1, m2 = n & 1;
    const int t = threadIdx.x;
    const int cg = t & 7, pg = t >> 3;     // 8 col-groups x 16 pixel-groups

    __shared__ __align__(16) float sB[64][64];
    __shared__ __align__(16) float sx[2][64][64];

    // load B (8 float4 per thread)
    {
        const float4* gB4 = (const float4*)(g_B + n * 4096);
#pragma unroll
        for (int ld = 0; ld < 8; ld++) {
            int idx = ld * 128 + t;
            *(float4*)&sB[idx >> 4][(idx & 15) * 4] = gB4[idx];
        }
    }

    const int PPC = 16384 / ACH;   // 256
    const int NIT = PPC / 64;      // 4
    const int p0  = ch * PPC;
    const int q = t & 15, plb = t >> 4;    // loader: 8 rows, q quad

    float4 rbuf[8];
    // prologue: pass0 load+store, pass1 load
#pragma unroll
    for (int ld = 0; ld < 8; ld++) {
        int p = p0 + ld * 8 + plb;
        rbuf[ld] = *((const float4*)(x + rowoff(bi, m1, m2, p)) + q);
    }
#pragma unroll
    for (int ld = 0; ld < 8; ld++) *(float4*)&sx[0][ld * 8 + plb][q * 4] = rbuf[ld];
#pragma unroll
    for (int ld = 0; ld < 8; ld++) {
        int p = p0 + 64 + ld * 8 + plb;
        rbuf[ld] = *((const float4*)(x + rowoff(bi, m1, m2, p)) + q);
    }
    __syncthreads();

    for (int pass = 0; pass < NIT; pass++) {
        const float (*buf)[64] = sx[pass & 1];
        ull acc[4][4];
#pragma unroll
        for (int i = 0; i < 4; i++)
#pragma unroll
            for (int m = 0; m < 4; m++) acc[i][m] = 0ull;

#pragma unroll 4
        for (int k0 = 0; k0 < 64; k0 += 4) {
            float4 xr[4];
#pragma unroll
            for (int i = 0; i < 4; i++) xr[i] = *(const float4*)&buf[pg * 4 + i][k0];
#pragma unroll
            for (int kk = 0; kk < 4; kk++) {
                ulonglong2 b01 = *(const ulonglong2*)&sB[k0 + kk][cg * 8];
                ulonglong2 b23 = *(const ulonglong2*)&sB[k0 + kk][cg * 8 + 4];
#pragma unroll
                for (int i = 0; i < 4; i++) {
                    float xv = (kk == 0) ? xr[i].x : (kk == 1) ? xr[i].y
                             : (kk == 2) ? xr[i].z : xr[i].w;
                    ull xd = pack2(xv, xv);
                    acc[i][0] = fma2(xd, b01.x, acc[i][0]);
                    acc[i][1] = fma2(xd, b01.y, acc[i][1]);
                    acc[i][2] = fma2(xd, b23.x, acc[i][2]);
                    acc[i][3] = fma2(xd, b23.y, acc[i][3]);
                }
            }
        }

        // store results (coalesced STG.128 x2 per pixel-row)
#pragma unroll
        for (int i = 0; i < 4; i++) {
            int p = p0 + pass * 64 + pg * 4 + i;
            float4 o0, o1;
            unpack2(acc[i][0], o0.x, o0.y);
            unpack2(acc[i][1], o0.z, o0.w);
            unpack2(acc[i][2], o1.x, o1.y);
            unpack2(acc[i][3], o1.z, o1.w);
            float* dst = out + rowoff(bi, m1, m2, p) + cg * 8;
            *(float4*)dst = o0;
            *(float4*)(dst + 4) = o1;
        }

        if (pass + 1 < NIT) {  // store staged data for pass+1
            int b = (pass + 1) & 1;
#pragma unroll
            for (int ld = 0; ld < 8; ld++)
                *(float4*)&sx[b][ld * 8 + plb][q * 4] = rbuf[ld];
        }
        if (pass + 2 < NIT) {  // load data for pass+2
#pragma unroll
            for (int ld = 0; ld < 8; ld++) {
                int p = p0 + (pass + 2) * 64 + ld * 8 + plb;
                rbuf[ld] = *((const float4*)(x + rowoff(bi, m1, m2, p)) + q);
            }
        }
        __syncthreads();
    }
}

extern "C" void kernel_launch(void* const* d_in, const int* in_sizes, int n_in,
                              void* d_out, int out_size) {
    const float* x     = (const float*)d_in[0];
    const float* Wqkv  = (const float*)d_in[1];
    const float* Wproj = (const float*)d_in[2];
    float* out = (float*)d_out;

    gram_kernel<<<dim3(GCH, 32), 256>>>(x);
    reduce_kernel<<<dim3(8, 32), 128>>>();
    block_math_kernel<<<32, 256>>>(Wqkv, Wproj);
    apply_kernel<<<dim3(ACH, 32), 128>>>(x, out);
}